// round 12
// baseline (speedup 1.0000x reference)
#include <cuda_runtime.h>
#include <cstdint>

#define IMAGE_H 200
#define IMAGE_W 200
#define ROW_BYTES (IMAGE_W * 3)              // 600 bytes = 150 u32 per row
#define ROW_U32   (ROW_BYTES / 4)            // 150
#define IMG_BYTES (IMAGE_H * ROW_BYTES)      // 120000 smem bytes per image
#define IMG_ELEMS IMG_BYTES                  // float elems per output image
#define N_U32 (IMG_BYTES / 4)                // 30000 u32 groups (= float4 outputs)
#define THREADS 1024

// Fused: hoisted zero prefix/suffix global stores (overlap all prologue),
// compose dirty-window uint8 rows in SMEM via closed-form Bresenham + markers,
// then stream the dirty middle as float32 with the minimal LDS->cvt->STG body.
// 1024 threads/block: 32 warps resident to deepen the outstanding-store pool.
__global__ void __launch_bounds__(THREADS) draw_rope_fused(
    const float* __restrict__ x,          // [M, 6] = (x0,y0,x1,y1,x2,y2)
    const float* __restrict__ resolution, // [2]
    const float* __restrict__ origin,     // [2]
    float* __restrict__ out)              // [M, 200, 200, 3] float32
{
    extern __shared__ unsigned char s_img[]; // IMG_BYTES

    const int m = blockIdx.x;

    // ---- rope point pixel indices (all threads, registers) ----
    const float res0 = resolution[0];
    const float res1 = resolution[1];
    const float org0 = origin[0];
    const float org1 = origin[1];
    const float* px = x + (size_t)m * 6;

    int rows[3], cols[3];
#pragma unroll
    for (int i = 0; i < 3; i++) {
        float xf = px[2 * i + 0];
        float yf = px[2 * i + 1];
        rows[i] = (int)floorf(yf / res0 + org0);
        cols[i] = (int)floorf(xf / res1 + org1);
    }

    // Dirty row window (segments share p1; each spans a contiguous row range).
    int Rmin = min(rows[0], min(rows[1], rows[2]));
    int Rmax = max(rows[0], max(rows[1], rows[2]));
    Rmin = max(0, min(Rmin, IMAGE_H - 1));
    Rmax = max(0, min(Rmax, IMAGE_H - 1));

    const int g_lo = Rmin * ROW_U32;          // first dirty u32 group
    const int g_hi = (Rmax + 1) * ROW_U32;    // one past last dirty u32 group

    float4* o4 = reinterpret_cast<float4*>(out + (size_t)m * IMG_ELEMS);
    const float4 zf = make_float4(0.f, 0.f, 0.f, 0.f);

    // ---- Phase A (hoisted): zero prefix + suffix of the OUTPUT directly.
    // Depends on nothing; the LSU drains these stores asynchronously while
    // the smem phases below run, keeping the store pipe busy through the
    // prologue and barriers.
    for (int i = threadIdx.x; i < g_lo; i += THREADS) __stcs(&o4[i], zf);
    for (int i = g_hi + threadIdx.x; i < N_U32; i += THREADS) __stcs(&o4[i], zf);

    // ---- Phase 0: zero smem over the dirty window only (STS.128) ----
    {
        const int b_lo = (g_lo * 4) / 16;                 // 16B-aligned down
        const int b_hi = (g_hi * 4 + 15) / 16;            // 16B-aligned up
        uint4 z = make_uint4(0u, 0u, 0u, 0u);
        uint4* s4 = reinterpret_cast<uint4*>(s_img);
        for (int i = b_lo + threadIdx.x; i < b_hi; i += THREADS) s4[i] = z;
    }

    __syncthreads(); // zero window complete

    // ---- Phase 1: closed-form Bresenham into smem ----
    // m_k = floor((2*k*minor + major) / (2*major)), pixels k = 0..major inclusive
#pragma unroll
    for (int s = 0; s < 2; s++) {
        const int c0 = cols[s],     r0 = rows[s];
        const int c1 = cols[s + 1], r1 = rows[s + 1];
        const int dx = abs(c1 - c0);
        const int D  = abs(r1 - r0);
        const int sc = (c0 < c1) ? 1 : -1;
        const int sr = (r0 < r1) ? 1 : -1;
        const bool xmajor = (dx >= D);
        const unsigned major = xmajor ? (unsigned)dx : (unsigned)D;
        const unsigned minor = xmajor ? (unsigned)D  : (unsigned)dx;

        if (major == 0u) {
            if (threadIdx.x == 0 &&
                (unsigned)r0 < (unsigned)IMAGE_H && (unsigned)c0 < (unsigned)IMAGE_W) {
                unsigned char* q = s_img + (r0 * IMAGE_W + c0) * 3;
                q[0] = 128; q[1] = 128; q[2] = 128;
            }
        } else {
            const unsigned den = 2u * major;
            for (unsigned k = threadIdx.x; k <= major; k += THREADS) {
                const int qs = (int)((2u * k * minor + major) / den);
                const int c = xmajor ? (c0 + (int)k * sc) : (c0 + qs * sc);
                const int r = xmajor ? (r0 + qs * sr) : (r0 + (int)k * sr);
                if ((unsigned)r < (unsigned)IMAGE_H && (unsigned)c < (unsigned)IMAGE_W) {
                    unsigned char* q = s_img + (r * IMAGE_W + c) * 3;
                    q[0] = 128; q[1] = 128; q[2] = 128;
                }
            }
        }
    }

    __syncthreads(); // line pixels done before marker overwrites

    // ---- Phase 2: endpoint markers, reference order: red, red, green ----
    if (threadIdx.x == 0) {
        const unsigned char R[3][3] = { {255, 0, 0}, {255, 0, 0}, {0, 255, 0} };
#pragma unroll
        for (int i = 0; i < 3; i++) {
            int r = rows[i], cidx = cols[i];
            if ((unsigned)r < (unsigned)IMAGE_H && (unsigned)cidx < (unsigned)IMAGE_W) {
                unsigned char* q = s_img + (r * IMAGE_W + cidx) * 3;
                q[0] = R[i][0]; q[1] = R[i][1]; q[2] = R[i][2];
            }
        }
    }

    __syncthreads(); // dirty window complete in smem

    // ---- Phase 3: stream dirty middle as float32 (minimal body) ----
    {
        const uint32_t* s32 = reinterpret_cast<const uint32_t*>(s_img);
#pragma unroll 2
        for (int i = g_lo + threadIdx.x; i < g_hi; i += THREADS) {
            uint32_t w = s32[i];
            float4 f;
            f.x = (float)( w        & 0xffu);
            f.y = (float)((w >> 8)  & 0xffu);
            f.z = (float)((w >> 16) & 0xffu);
            f.w = (float)( w >> 24        );
            __stcs(&o4[i], f);
        }
    }
}

extern "C" void kernel_launch(void* const* d_in, const int* in_sizes, int n_in,
                              void* d_out, int out_size) {
    const float* x          = (const float*)d_in[0]; // [B*T*6] float32
    const float* resolution = (const float*)d_in[1]; // [2]
    const float* origin     = (const float*)d_in[2]; // [2]
    float* out              = (float*)d_out;         // [B,T,200,200,3] float32

    const int M = in_sizes[0] / 6; // B*T = 800 images

    cudaFuncSetAttribute(draw_rope_fused,
                         cudaFuncAttributeMaxDynamicSharedMemorySize, IMG_BYTES);
    draw_rope_fused<<<M, THREADS, IMG_BYTES>>>(x, resolution, origin, out);
}

// round 13
// speedup vs baseline: 1.0221x; 1.0221x over previous
#include <cuda_runtime.h>
#include <cstdint>

#define IMAGE_H 200
#define IMAGE_W 200
#define ROW_BYTES (IMAGE_W * 3)              // 600 bytes = 150 u32 per row
#define ROW_U32   (ROW_BYTES / 4)            // 150
#define IMG_BYTES (IMAGE_H * ROW_BYTES)      // 120000 smem bytes per image
#define IMG_ELEMS IMG_BYTES                  // float elems per output image
#define N_U32 (IMG_BYTES / 4)                // 30000 u32 groups (= float4 outputs)
#define THREADS 512

// Fused: hoisted zero prefix/suffix global stores (overlap all prologue),
// compose dirty-window uint8 rows in SMEM via closed-form Bresenham + markers,
// then stream the dirty middle as float32 with the minimal LDS->cvt->STG body.
__global__ void __launch_bounds__(THREADS) draw_rope_fused(
    const float* __restrict__ x,          // [M, 6] = (x0,y0,x1,y1,x2,y2)
    const float* __restrict__ resolution, // [2]
    const float* __restrict__ origin,     // [2]
    float* __restrict__ out)              // [M, 200, 200, 3] float32
{
    extern __shared__ unsigned char s_img[]; // IMG_BYTES

    const int m = blockIdx.x;

    // ---- rope point pixel indices (all threads, registers) ----
    const float res0 = resolution[0];
    const float res1 = resolution[1];
    const float org0 = origin[0];
    const float org1 = origin[1];
    const float* px = x + (size_t)m * 6;

    int rows[3], cols[3];
#pragma unroll
    for (int i = 0; i < 3; i++) {
        float xf = px[2 * i + 0];
        float yf = px[2 * i + 1];
        rows[i] = (int)floorf(yf / res0 + org0);
        cols[i] = (int)floorf(xf / res1 + org1);
    }

    // Dirty row window (segments share p1; each spans a contiguous row range).
    int Rmin = min(rows[0], min(rows[1], rows[2]));
    int Rmax = max(rows[0], max(rows[1], rows[2]));
    Rmin = max(0, min(Rmin, IMAGE_H - 1));
    Rmax = max(0, min(Rmax, IMAGE_H - 1));

    const int g_lo = Rmin * ROW_U32;          // first dirty u32 group
    const int g_hi = (Rmax + 1) * ROW_U32;    // one past last dirty u32 group

    float4* o4 = reinterpret_cast<float4*>(out + (size_t)m * IMG_ELEMS);
    const float4 zf = make_float4(0.f, 0.f, 0.f, 0.f);

    // ---- Phase A (hoisted): zero prefix + suffix of the OUTPUT directly.
    // Depends on nothing; the LSU drains these stores asynchronously while
    // the smem phases below run, keeping the store pipe busy through the
    // prologue and barriers.
    for (int i = threadIdx.x; i < g_lo; i += THREADS) __stcs(&o4[i], zf);
    for (int i = g_hi + threadIdx.x; i < N_U32; i += THREADS) __stcs(&o4[i], zf);

    // ---- Phase 0: zero smem over the dirty window only (STS.128) ----
    {
        const int b_lo = (g_lo * 4) / 16;                 // 16B-aligned down
        const int b_hi = (g_hi * 4 + 15) / 16;            // 16B-aligned up
        uint4 z = make_uint4(0u, 0u, 0u, 0u);
        uint4* s4 = reinterpret_cast<uint4*>(s_img);
        for (int i = b_lo + threadIdx.x; i < b_hi; i += THREADS) s4[i] = z;
    }

    __syncthreads(); // zero window complete

    // ---- Phase 1: closed-form Bresenham into smem ----
    // m_k = floor((2*k*minor + major) / (2*major)), pixels k = 0..major inclusive
#pragma unroll
    for (int s = 0; s < 2; s++) {
        const int c0 = cols[s],     r0 = rows[s];
        const int c1 = cols[s + 1], r1 = rows[s + 1];
        const int dx = abs(c1 - c0);
        const int D  = abs(r1 - r0);
        const int sc = (c0 < c1) ? 1 : -1;
        const int sr = (r0 < r1) ? 1 : -1;
        const bool xmajor = (dx >= D);
        const unsigned major = xmajor ? (unsigned)dx : (unsigned)D;
        const unsigned minor = xmajor ? (unsigned)D  : (unsigned)dx;

        if (major == 0u) {
            if (threadIdx.x == 0 &&
                (unsigned)r0 < (unsigned)IMAGE_H && (unsigned)c0 < (unsigned)IMAGE_W) {
                unsigned char* q = s_img + (r0 * IMAGE_W + c0) * 3;
                q[0] = 128; q[1] = 128; q[2] = 128;
            }
        } else {
            const unsigned den = 2u * major;
            for (unsigned k = threadIdx.x; k <= major; k += THREADS) {
                const int qs = (int)((2u * k * minor + major) / den);
                const int c = xmajor ? (c0 + (int)k * sc) : (c0 + qs * sc);
                const int r = xmajor ? (r0 + qs * sr) : (r0 + (int)k * sr);
                if ((unsigned)r < (unsigned)IMAGE_H && (unsigned)c < (unsigned)IMAGE_W) {
                    unsigned char* q = s_img + (r * IMAGE_W + c) * 3;
                    q[0] = 128; q[1] = 128; q[2] = 128;
                }
            }
        }
    }

    __syncthreads(); // line pixels done before marker overwrites

    // ---- Phase 2: endpoint markers, reference order: red, red, green ----
    if (threadIdx.x == 0) {
        const unsigned char R[3][3] = { {255, 0, 0}, {255, 0, 0}, {0, 255, 0} };
#pragma unroll
        for (int i = 0; i < 3; i++) {
            int r = rows[i], cidx = cols[i];
            if ((unsigned)r < (unsigned)IMAGE_H && (unsigned)cidx < (unsigned)IMAGE_W) {
                unsigned char* q = s_img + (r * IMAGE_W + cidx) * 3;
                q[0] = R[i][0]; q[1] = R[i][1]; q[2] = R[i][2];
            }
        }
    }

    __syncthreads(); // dirty window complete in smem

    // ---- Phase 3: stream dirty middle as float32 (minimal body) ----
    {
        const uint32_t* s32 = reinterpret_cast<const uint32_t*>(s_img);
        for (int i = g_lo + threadIdx.x; i < g_hi; i += THREADS) {
            uint32_t w = s32[i];
            float4 f;
            f.x = (float)( w        & 0xffu);
            f.y = (float)((w >> 8)  & 0xffu);
            f.z = (float)((w >> 16) & 0xffu);
            f.w = (float)( w >> 24        );
            __stcs(&o4[i], f);
        }
    }
}

extern "C" void kernel_launch(void* const* d_in, const int* in_sizes, int n_in,
                              void* d_out, int out_size) {
    const float* x          = (const float*)d_in[0]; // [B*T*6] float32
    const float* resolution = (const float*)d_in[1]; // [2]
    const float* origin     = (const float*)d_in[2]; // [2]
    float* out              = (float*)d_out;         // [B,T,200,200,3] float32

    const int M = in_sizes[0] / 6; // B*T = 800 images

    cudaFuncSetAttribute(draw_rope_fused,
                         cudaFuncAttributeMaxDynamicSharedMemorySize, IMG_BYTES);
    draw_rope_fused<<<M, THREADS, IMG_BYTES>>>(x, resolution, origin, out);
}

// round 14
// speedup vs baseline: 1.0498x; 1.0271x over previous
#include <cuda_runtime.h>
#include <cstdint>

#define IMAGE_H 200
#define IMAGE_W 200
#define ROW_BYTES (IMAGE_W * 3)              // 600 bytes = 150 u32 per row
#define ROW_U32   (ROW_BYTES / 4)            // 150
#define IMG_BYTES (IMAGE_H * ROW_BYTES)      // 120000 smem bytes per image
#define IMG_ELEMS IMG_BYTES                  // float elems per output image
#define N_U32 (IMG_BYTES / 4)                // 30000 u32 groups (= float4 outputs)
#define THREADS 512

// Fused: hoisted zero prefix/suffix global stores (overlap all prologue),
// compose dirty-window uint8 rows in SMEM via closed-form Bresenham + markers,
// then stream the dirty middle as float32 with the minimal LDS->cvt->STG body.
__global__ void __launch_bounds__(THREADS) draw_rope_fused(
    const float* __restrict__ x,          // [M, 6] = (x0,y0,x1,y1,x2,y2)
    const float* __restrict__ resolution, // [2]
    const float* __restrict__ origin,     // [2]
    float* __restrict__ out)              // [M, 200, 200, 3] float32
{
    extern __shared__ unsigned char s_img[]; // IMG_BYTES

    const int m = blockIdx.x;

    // ---- rope point pixel indices (all threads, registers) ----
    const float res0 = resolution[0];
    const float res1 = resolution[1];
    const float org0 = origin[0];
    const float org1 = origin[1];
    const float* px = x + (size_t)m * 6;

    int rows[3], cols[3];
#pragma unroll
    for (int i = 0; i < 3; i++) {
        float xf = px[2 * i + 0];
        float yf = px[2 * i + 1];
        rows[i] = (int)floorf(yf / res0 + org0);
        cols[i] = (int)floorf(xf / res1 + org1);
    }

    // Dirty row window (segments share p1; each spans a contiguous row range).
    int Rmin = min(rows[0], min(rows[1], rows[2]));
    int Rmax = max(rows[0], max(rows[1], rows[2]));
    Rmin = max(0, min(Rmin, IMAGE_H - 1));
    Rmax = max(0, min(Rmax, IMAGE_H - 1));

    const int g_lo = Rmin * ROW_U32;          // first dirty u32 group
    const int g_hi = (Rmax + 1) * ROW_U32;    // one past last dirty u32 group

    float4* o4 = reinterpret_cast<float4*>(out + (size_t)m * IMG_ELEMS);
    const float4 zf = make_float4(0.f, 0.f, 0.f, 0.f);

    // ---- Phase A (hoisted): zero prefix + suffix of the OUTPUT directly.
    // Depends on nothing; the LSU drains these stores asynchronously while
    // the smem phases below run. unroll 4: front-batch independent STG.128s
    // per scheduler visit to fill the store queue faster.
#pragma unroll 4
    for (int i = threadIdx.x; i < g_lo; i += THREADS) __stcs(&o4[i], zf);
#pragma unroll 4
    for (int i = g_hi + threadIdx.x; i < N_U32; i += THREADS) __stcs(&o4[i], zf);

    // ---- Phase 0: zero smem over the dirty window only (STS.128) ----
    {
        const int b_lo = (g_lo * 4) / 16;                 // 16B-aligned down
        const int b_hi = (g_hi * 4 + 15) / 16;            // 16B-aligned up
        uint4 z = make_uint4(0u, 0u, 0u, 0u);
        uint4* s4 = reinterpret_cast<uint4*>(s_img);
        for (int i = b_lo + threadIdx.x; i < b_hi; i += THREADS) s4[i] = z;
    }

    __syncthreads(); // zero window complete

    // ---- Phase 1: closed-form Bresenham into smem ----
    // m_k = floor((2*k*minor + major) / (2*major)), pixels k = 0..major inclusive
#pragma unroll
    for (int s = 0; s < 2; s++) {
        const int c0 = cols[s],     r0 = rows[s];
        const int c1 = cols[s + 1], r1 = rows[s + 1];
        const int dx = abs(c1 - c0);
        const int D  = abs(r1 - r0);
        const int sc = (c0 < c1) ? 1 : -1;
        const int sr = (r0 < r1) ? 1 : -1;
        const bool xmajor = (dx >= D);
        const unsigned major = xmajor ? (unsigned)dx : (unsigned)D;
        const unsigned minor = xmajor ? (unsigned)D  : (unsigned)dx;

        if (major == 0u) {
            if (threadIdx.x == 0 &&
                (unsigned)r0 < (unsigned)IMAGE_H && (unsigned)c0 < (unsigned)IMAGE_W) {
                unsigned char* q = s_img + (r0 * IMAGE_W + c0) * 3;
                q[0] = 128; q[1] = 128; q[2] = 128;
            }
        } else {
            const unsigned den = 2u * major;
            for (unsigned k = threadIdx.x; k <= major; k += THREADS) {
                const int qs = (int)((2u * k * minor + major) / den);
                const int c = xmajor ? (c0 + (int)k * sc) : (c0 + qs * sc);
                const int r = xmajor ? (r0 + qs * sr) : (r0 + (int)k * sr);
                if ((unsigned)r < (unsigned)IMAGE_H && (unsigned)c < (unsigned)IMAGE_W) {
                    unsigned char* q = s_img + (r * IMAGE_W + c) * 3;
                    q[0] = 128; q[1] = 128; q[2] = 128;
                }
            }
        }
    }

    __syncthreads(); // line pixels done before marker overwrites

    // ---- Phase 2: endpoint markers, reference order: red, red, green ----
    if (threadIdx.x == 0) {
        const unsigned char R[3][3] = { {255, 0, 0}, {255, 0, 0}, {0, 255, 0} };
#pragma unroll
        for (int i = 0; i < 3; i++) {
            int r = rows[i], cidx = cols[i];
            if ((unsigned)r < (unsigned)IMAGE_H && (unsigned)cidx < (unsigned)IMAGE_W) {
                unsigned char* q = s_img + (r * IMAGE_W + cidx) * 3;
                q[0] = R[i][0]; q[1] = R[i][1]; q[2] = R[i][2];
            }
        }
    }

    __syncthreads(); // dirty window complete in smem

    // ---- Phase 3: stream dirty middle as float32 (minimal body) ----
    {
        const uint32_t* s32 = reinterpret_cast<const uint32_t*>(s_img);
        for (int i = g_lo + threadIdx.x; i < g_hi; i += THREADS) {
            uint32_t w = s32[i];
            float4 f;
            f.x = (float)( w        & 0xffu);
            f.y = (float)((w >> 8)  & 0xffu);
            f.z = (float)((w >> 16) & 0xffu);
            f.w = (float)( w >> 24        );
            __stcs(&o4[i], f);
        }
    }
}

extern "C" void kernel_launch(void* const* d_in, const int* in_sizes, int n_in,
                              void* d_out, int out_size) {
    const float* x          = (const float*)d_in[0]; // [B*T*6] float32
    const float* resolution = (const float*)d_in[1]; // [2]
    const float* origin     = (const float*)d_in[2]; // [2]
    float* out              = (float*)d_out;         // [B,T,200,200,3] float32

    const int M = in_sizes[0] / 6; // B*T = 800 images

    cudaFuncSetAttribute(draw_rope_fused,
                         cudaFuncAttributeMaxDynamicSharedMemorySize, IMG_BYTES);
    draw_rope_fused<<<M, THREADS, IMG_BYTES>>>(x, resolution, origin, out);
}